// round 1
// baseline (speedup 1.0000x reference)
#include <cuda_runtime.h>
#include <math.h>

#define D 128
#define MAXN 100000
#define MAXE 600000
#define BM 64
#define LTHREADS 256

typedef unsigned long long ull;

// ---------------- static device scratch (no allocs allowed) ----------------
__device__ float g_h0[(size_t)MAXN * D];
__device__ float g_h1[(size_t)MAXN * D];
__device__ int   g_cnt[MAXN];
__device__ int   g_off[MAXN + 1];
__device__ int   g_cur[MAXN];
__device__ int   g_src[MAXE];

// ---------------- packed f32x2 helpers (Blackwell FFMA2) ----------------
__device__ __forceinline__ ull fma2(ull a, ull b, ull c) {
    ull d;
    asm("fma.rn.f32x2 %0, %1, %2, %3;" : "=l"(d) : "l"(a), "l"(b), "l"(c));
    return d;
}
__device__ __forceinline__ ull bcast2(float a) {
    ull d; unsigned int ai = __float_as_uint(a);
    asm("mov.b64 %0, {%1, %2};" : "=l"(d) : "r"(ai), "r"(ai));
    return d;
}
__device__ __forceinline__ void unpack2(ull v, float& lo, float& hi) {
    unsigned int l, h;
    asm("mov.b64 {%0, %1}, %2;" : "=r"(l), "=r"(h) : "l"(v));
    lo = __uint_as_float(l); hi = __uint_as_float(h);
}

// ---------------- CSR construction ----------------
__global__ void zero_cnt_kernel(int* cnt, int N) {
    int i = blockIdx.x * blockDim.x + threadIdx.x;
    if (i < N) cnt[i] = 0;
}

__global__ void count_kernel(const int* __restrict__ dst, int* cnt, int E) {
    int e = blockIdx.x * blockDim.x + threadIdx.x;
    if (e < E) atomicAdd(&cnt[dst[e]], 1);
}

// single-block exclusive scan over N counts -> off, cursor
__global__ void scan_kernel(const int* __restrict__ cnt, int* off, int* cur, int N) {
    __shared__ int part[1024];
    int t = threadIdx.x;
    int chunk = (N + 1023) / 1024;
    int s = t * chunk;
    int e = min(s + chunk, N);
    int sum = 0;
    for (int i = s; i < e; ++i) sum += cnt[i];
    part[t] = sum;
    __syncthreads();
    for (int d = 1; d < 1024; d <<= 1) {
        int v = (t >= d) ? part[t - d] : 0;
        __syncthreads();
        part[t] += v;
        __syncthreads();
    }
    int run = (t == 0) ? 0 : part[t - 1];
    for (int i = s; i < e; ++i) {
        off[i] = run;
        cur[i] = run;
        run += cnt[i];
    }
    if (t == 1023) off[N] = part[1023];
}

__global__ void fill_kernel(const int* __restrict__ src, const int* __restrict__ dst,
                            int* cur, int* out, int E) {
    int e = blockIdx.x * blockDim.x + threadIdx.x;
    if (e < E) {
        int d = dst[e];
        int pos = atomicAdd(&cur[d], 1);
        out[pos] = src[e];
    }
}

// ---------------- fused SAGE layer: aggregate + dual GEMM + bias + relu ----------------
// C[v,:] = relu( mean_nbrs(h)[v,:] @ Wl + h[v,:] @ Wr + b )
__global__ __launch_bounds__(LTHREADS) void layer_kernel(
    const float* __restrict__ h_in, float* __restrict__ h_out,
    const float* __restrict__ Wl, const float* __restrict__ Wr,
    const float* __restrict__ bias,
    const int* __restrict__ off, const int* __restrict__ srcs, int N)
{
    extern __shared__ float smem[];
    float (*Am)[D + 4] = (float (*)[D + 4])smem;                    // mean rows
    float (*Ah)[D + 4] = (float (*)[D + 4])(smem + BM * (D + 4));   // own rows

    const int t = threadIdx.x;
    const int lane = t & 31, warp = t >> 5;
    const int row0 = blockIdx.x * BM;

    // stage own 64 rows (coalesced)
    for (int i = t; i < BM * (D / 4); i += LTHREADS) {
        int r = i >> 5;
        int c4 = (i & 31) << 2;
        float4 v = make_float4(0.f, 0.f, 0.f, 0.f);
        if (row0 + r < N)
            v = *(const float4*)(h_in + (size_t)(row0 + r) * D + c4);
        *(float4*)&Ah[r][c4] = v;
    }

    // CSR gather + mean: warp w handles rows [w*8, w*8+8), lane covers 4 cols
    for (int j = 0; j < BM / 8; ++j) {
        int r = warp * 8 + j;
        int v = row0 + r;
        float4 acc = make_float4(0.f, 0.f, 0.f, 0.f);
        if (v < N) {
            int s = off[v];
            int e = off[v + 1];
            for (int k = s; k < e; ++k) {
                int u = __ldg(&srcs[k]);
                float4 hv = __ldg((const float4*)(h_in + (size_t)u * D + lane * 4));
                acc.x += hv.x; acc.y += hv.y; acc.z += hv.z; acc.w += hv.w;
            }
            float ic = 1.0f / (float)max(e - s, 1);
            acc.x *= ic; acc.y *= ic; acc.z *= ic; acc.w *= ic;
        }
        *(float4*)&Am[r][lane * 4] = acc;
    }
    __syncthreads();

    // dual GEMM: thread (tr,tc) computes rows {tr, tr+16, tr+32, tr+48} x cols [tc*8, tc*8+8)
    const int tr = t >> 4;
    const int tc = t & 15;

    ull acc[4][4];
#pragma unroll
    for (int i = 0; i < 4; ++i)
#pragma unroll
        for (int j = 0; j < 4; ++j) acc[i][j] = 0ull;

    const ull* WlP = (const ull*)Wl;
    const ull* WrP = (const ull*)Wr;

#pragma unroll 2
    for (int k = 0; k < D; ++k) {
        ull am[4], ah[4];
#pragma unroll
        for (int i = 0; i < 4; ++i) {
            am[i] = bcast2(Am[tr + 16 * i][k]);
            ah[i] = bcast2(Ah[tr + 16 * i][k]);
        }
        int base = (k * D + tc * 8) >> 1;   // index in f32x2 pairs
        ulonglong2 l0 = __ldg((const ulonglong2*)(WlP + base));
        ulonglong2 l1 = __ldg((const ulonglong2*)(WlP + base + 2));
        ulonglong2 r0 = __ldg((const ulonglong2*)(WrP + base));
        ulonglong2 r1 = __ldg((const ulonglong2*)(WrP + base + 2));
        ull wl[4] = {l0.x, l0.y, l1.x, l1.y};
        ull wr[4] = {r0.x, r0.y, r1.x, r1.y};
#pragma unroll
        for (int i = 0; i < 4; ++i) {
#pragma unroll
            for (int j = 0; j < 4; ++j) {
                acc[i][j] = fma2(am[i], wl[j], acc[i][j]);
                acc[i][j] = fma2(ah[i], wr[j], acc[i][j]);
            }
        }
    }

    // epilogue: bias + relu + store
    float4 b0 = __ldg((const float4*)(bias + tc * 8));
    float4 b1 = __ldg((const float4*)(bias + tc * 8 + 4));
    float bl[8] = {b0.x, b0.y, b0.z, b0.w, b1.x, b1.y, b1.z, b1.w};

#pragma unroll
    for (int i = 0; i < 4; ++i) {
        int gr = row0 + tr + 16 * i;
        if (gr >= N) continue;
        float o[8];
#pragma unroll
        for (int j = 0; j < 4; ++j) unpack2(acc[i][j], o[2 * j], o[2 * j + 1]);
#pragma unroll
        for (int c = 0; c < 8; ++c) o[c] = fmaxf(o[c] + bl[c], 0.0f);
        float* outp = h_out + (size_t)gr * D + tc * 8;
        *(float4*)(outp)     = make_float4(o[0], o[1], o[2], o[3]);
        *(float4*)(outp + 4) = make_float4(o[4], o[5], o[6], o[7]);
    }
}

// ---------------- pooled sum (sorted batch, binary-search bounds) + sigmoid head ----------------
__global__ void pool_head_kernel(const float* __restrict__ h, const int* __restrict__ batch,
                                 const float* __restrict__ Wro, const float* __restrict__ bro,
                                 float* __restrict__ out, int N)
{
    __shared__ int bounds[2];
    __shared__ float red[4];
    int g = blockIdx.x;
    int t = threadIdx.x;   // 128 threads, t = feature column

    if (t < 2) {
        int target = g + t;
        int lo = 0, hi = N;
        while (lo < hi) {
            int mid = (lo + hi) >> 1;
            if (batch[mid] < target) lo = mid + 1; else hi = mid;
        }
        bounds[t] = lo;
    }
    __syncthreads();
    int s = bounds[0], e = bounds[1];

    float sum = 0.0f;
    for (int v = s; v < e; ++v) sum += h[(size_t)v * D + t];
    float val = sum * __ldg(&Wro[t]);
#pragma unroll
    for (int o = 16; o > 0; o >>= 1) val += __shfl_xor_sync(0xffffffff, val, o);
    if ((t & 31) == 0) red[t >> 5] = val;
    __syncthreads();
    if (t == 0) {
        float z = red[0] + red[1] + red[2] + red[3] + __ldg(bro);
        out[g] = 1.0f / (1.0f + expf(-z));
    }
}

// ---------------- launcher ----------------
extern "C" void kernel_launch(void* const* d_in, const int* in_sizes, int n_in,
                              void* d_out, int out_size)
{
    const float* x     = (const float*)d_in[0];
    const int*   ei    = (const int*)d_in[1];
    const int*   batch = (const int*)d_in[2];
    const float* Wl1 = (const float*)d_in[3];
    const float* Wr1 = (const float*)d_in[4];
    const float* b1  = (const float*)d_in[5];
    const float* Wl2 = (const float*)d_in[6];
    const float* Wr2 = (const float*)d_in[7];
    const float* b2  = (const float*)d_in[8];
    const float* Wl3 = (const float*)d_in[9];
    const float* Wr3 = (const float*)d_in[10];
    const float* b3  = (const float*)d_in[11];
    const float* Wro = (const float*)d_in[12];
    const float* bro = (const float*)d_in[13];
    float* out = (float*)d_out;

    int N = in_sizes[0] / D;
    int E = in_sizes[1] / 2;
    int G = out_size;

    float *h0, *h1;
    int *cnt, *off, *cur, *srcs;
    cudaGetSymbolAddress((void**)&h0,   g_h0);
    cudaGetSymbolAddress((void**)&h1,   g_h1);
    cudaGetSymbolAddress((void**)&cnt,  g_cnt);
    cudaGetSymbolAddress((void**)&off,  g_off);
    cudaGetSymbolAddress((void**)&cur,  g_cur);
    cudaGetSymbolAddress((void**)&srcs, g_src);

    const int* src_arr = ei;
    const int* dst_arr = ei + E;

    // CSR build
    zero_cnt_kernel<<<(N + 255) / 256, 256>>>(cnt, N);
    count_kernel<<<(E + 255) / 256, 256>>>(dst_arr, cnt, E);
    scan_kernel<<<1, 1024>>>(cnt, off, cur, N);
    fill_kernel<<<(E + 255) / 256, 256>>>(src_arr, dst_arr, cur, srcs, E);

    // fused SAGE layers
    int smem = 2 * BM * (D + 4) * sizeof(float);
    cudaFuncSetAttribute((const void*)layer_kernel,
                         cudaFuncAttributeMaxDynamicSharedMemorySize, smem);
    int lblocks = (N + BM - 1) / BM;
    layer_kernel<<<lblocks, LTHREADS, smem>>>(x,  h0, Wl1, Wr1, b1, off, srcs, N);
    layer_kernel<<<lblocks, LTHREADS, smem>>>(h0, h1, Wl2, Wr2, b2, off, srcs, N);
    layer_kernel<<<lblocks, LTHREADS, smem>>>(h1, h0, Wl3, Wr3, b3, off, srcs, N);

    // pooling + head
    pool_head_kernel<<<G, D>>>(h0, batch, Wro, bro, out, N);
}